// round 15
// baseline (speedup 1.0000x reference)
#include <cuda_runtime.h>
#include <cuda_bf16.h>
#include <cuda_fp16.h>
#include <cstdint>

#define M1 768
#define M2 768
#define HID 1024
#define ATTN 256

// ---------------- scratch (no cudaMalloc allowed) ----------------
__device__ float g_x1[M1 * ATTN];
__device__ float g_x2[M2 * ATTN];
__device__ __align__(4) __half2 g_x1h[M1 * ATTN / 2];
__device__ __align__(4) __half2 g_x2h[M2 * ATTN / 2];
__device__ float g_rowsum[M1];
__device__ float g_colsum[M2];
__device__ __align__(16) __nv_bfloat16 g_h_hi[2][M1 * HID];
__device__ __align__(16) __nv_bfloat16 g_h_lo[2][M1 * HID];
__device__ __align__(16) __nv_bfloat16 g_w_hi[2][ATTN * HID];
__device__ __align__(16) __nv_bfloat16 g_w_lo[2][ATTN * HID];

// ---------------- helpers ----------------
__device__ __forceinline__ uint32_t smem_to_u32(const void* p) {
    uint32_t a;
    asm("{ .reg .u64 t; cvta.to.shared.u64 t, %1; cvt.u32.u64 %0, t; }" : "=r"(a) : "l"(p));
    return a;
}
__device__ __forceinline__ __half2 tanh2_fast(__half2 x) {
    __half2 r;
    asm("tanh.approx.f16x2 %0, %1;" : "=r"(*(uint32_t*)&r) : "r"(*(const uint32_t*)&x));
    return r;
}
__device__ __forceinline__ uint32_t pack_bf16x2(float lo, float hi) {
    uint32_t r;
    asm("cvt.rn.bf16x2.f32 %0, %1, %2;" : "=r"(r) : "f"(hi), "f"(lo));
    return r;
}

#define CP_ASYNC_16(dst, src) \
    asm volatile("cp.async.cg.shared.global [%0], [%1], 16;" :: "r"(dst), "l"(src) : "memory")
#define CP_ASYNC_COMMIT() asm volatile("cp.async.commit_group;" ::: "memory")
#define CP_ASYNC_WAIT(n)  asm volatile("cp.async.wait_group %0;" :: "n"(n) : "memory")

#define LDSM_X4(r0, r1, r2, r3, addr) \
    asm volatile("ldmatrix.sync.aligned.m8n8.x4.shared.b16 {%0,%1,%2,%3}, [%4];" \
                 : "=r"(r0), "=r"(r1), "=r"(r2), "=r"(r3) : "r"(addr))
// B tile is [n][k] with k contiguous (== col-major B for mma row.col):
// NON-transposed ldmatrix yields exactly the mma B fragment mapping.
#define LDSM_X2(r0, r1, addr) \
    asm volatile("ldmatrix.sync.aligned.m8n8.x2.shared.b16 {%0,%1}, [%2];" \
                 : "=r"(r0), "=r"(r1) : "r"(addr))

#define MMA_16816(d0, d1, d2, d3, a0, a1, a2, a3, b0, b1) \
    asm volatile("mma.sync.aligned.m16n8k16.row.col.f32.bf16.bf16.f32 " \
                 "{%0,%1,%2,%3}, {%4,%5,%6,%7}, {%8,%9}, {%0,%1,%2,%3};" \
                 : "+f"(d0), "+f"(d1), "+f"(d2), "+f"(d3) \
                 : "r"(a0), "r"(a1), "r"(a2), "r"(a3), "r"(b0), "r"(b1))

// ---------------------------------------------------------------------------
// Kernel 0: fp32 -> bf16 hi/lo split (vectorized); zero d_out.
// ---------------------------------------------------------------------------
__global__ __launch_bounds__(512) void convert_kernel(
    const float* __restrict__ h1, const float* __restrict__ h2,
    const float* __restrict__ W1, const float* __restrict__ W2,
    float* __restrict__ out)
{
    if (blockIdx.x == 0) out[threadIdx.x] = 0.0f;   // out_size == 512

    const int i = blockIdx.x * blockDim.x + threadIdx.x;   // 0 .. 393215
    uint32_t* __restrict__ hh0 = (uint32_t*)g_h_hi[0];
    uint32_t* __restrict__ hl0 = (uint32_t*)g_h_lo[0];
    uint32_t* __restrict__ hh1 = (uint32_t*)g_h_hi[1];
    uint32_t* __restrict__ hl1 = (uint32_t*)g_h_lo[1];
    {
        float2 x = ((const float2*)h1)[i];
        float a = __bfloat162float(__float2bfloat16(x.x));
        float b = __bfloat162float(__float2bfloat16(x.y));
        hh0[i] = pack_bf16x2(a, b);
        hl0[i] = pack_bf16x2(x.x - a, x.y - b);
        x = ((const float2*)h2)[i];
        a = __bfloat162float(__float2bfloat16(x.x));
        b = __bfloat162float(__float2bfloat16(x.y));
        hh1[i] = pack_bf16x2(a, b);
        hl1[i] = pack_bf16x2(x.x - a, x.y - b);
    }
    if (i < ATTN * HID / 2) {
        uint32_t* __restrict__ wh0 = (uint32_t*)g_w_hi[0];
        uint32_t* __restrict__ wl0 = (uint32_t*)g_w_lo[0];
        uint32_t* __restrict__ wh1 = (uint32_t*)g_w_hi[1];
        uint32_t* __restrict__ wl1 = (uint32_t*)g_w_lo[1];
        float2 x = ((const float2*)W1)[i];
        float a = __bfloat162float(__float2bfloat16(x.x));
        float b = __bfloat162float(__float2bfloat16(x.y));
        wh0[i] = pack_bf16x2(a, b);
        wl0[i] = pack_bf16x2(x.x - a, x.y - b);
        x = ((const float2*)W2)[i];
        a = __bfloat162float(__float2bfloat16(x.x));
        b = __bfloat162float(__float2bfloat16(x.y));
        wh1[i] = pack_bf16x2(a, b);
        wl1[i] = pack_bf16x2(x.x - a, x.y - b);
    }
}

// ---------------------------------------------------------------------------
// Kernel 1: bf16 mma.sync GEMM, 3-term hi/lo compensation. (unchanged)
// ---------------------------------------------------------------------------
#define AROW 144
#define SZ_T (64 * AROW)
#define BUF_SZ (4 * SZ_T)
#define GEMM_SMEM_BYTES (2 * BUF_SZ + 16)

__global__ __launch_bounds__(256) void gemm_kernel(
    const float* __restrict__ bias1, const float* __restrict__ bias2)
{
    extern __shared__ char dsm[];
    const uint32_t smem = smem_to_u32(dsm);

    const int tid  = threadIdx.x;
    const int lane = tid & 31;
    const int wid  = tid >> 5;
    const int wm   = wid & 3;
    const int wn   = wid >> 2;

    const int z  = blockIdx.z;
    const int m0 = blockIdx.y * 64;
    const int a0 = blockIdx.x * 64;

    const __nv_bfloat16* __restrict__ Ahg = g_h_hi[z];
    const __nv_bfloat16* __restrict__ Alg = g_h_lo[z];
    const __nv_bfloat16* __restrict__ Bhg = g_w_hi[z];
    const __nv_bfloat16* __restrict__ Blg = g_w_lo[z];
    const float* __restrict__ bias = z ? bias2 : bias1;
    float* __restrict__ xout = z ? g_x2 : g_x1;
    __half2* __restrict__ xouth = z ? g_x2h : g_x1h;

    auto load_chunk = [&](int c) {
        const int k0 = c * 64;
        const uint32_t buf = smem + (c & 1) * BUF_SZ;
#pragma unroll
        for (int it = 0; it < 2; it++) {
            const int s = tid + it * 256;
            const int r = s >> 3, cc = s & 7;
            const uint32_t so = r * AROW + cc * 16;
            CP_ASYNC_16(buf + so,              Ahg + (m0 + r) * HID + k0 + cc * 8);
            CP_ASYNC_16(buf + SZ_T + so,       Alg + (m0 + r) * HID + k0 + cc * 8);
            CP_ASYNC_16(buf + 2 * SZ_T + so,   Bhg + (a0 + r) * HID + k0 + cc * 8);
            CP_ASYNC_16(buf + 3 * SZ_T + so,   Blg + (a0 + r) * HID + k0 + cc * 8);
        }
        CP_ASYNC_COMMIT();
    };

    float acc[4][4];
#pragma unroll
    for (int ni = 0; ni < 4; ni++)
#pragma unroll
        for (int q = 0; q < 4; q++) acc[ni][q] = 0.0f;

    const uint32_t a_lane_off = (wm * 16 + (lane & 15)) * AROW + ((lane >> 4) * 16);
    const uint32_t b_lane_off = (wn * 32 + (lane & 7)) * AROW + (((lane >> 3) & 1) * 16);

    load_chunk(0);

    for (int c = 0; c < 16; c++) {
        if (c + 1 < 16) {
            load_chunk(c + 1);
            CP_ASYNC_WAIT(1);
        } else {
            CP_ASYNC_WAIT(0);
        }
        __syncthreads();

        const uint32_t buf = smem + (c & 1) * BUF_SZ;
        const uint32_t sAh = buf + a_lane_off;
        const uint32_t sAl = buf + SZ_T + a_lane_off;
        const uint32_t sBh = buf + 2 * SZ_T + b_lane_off;
        const uint32_t sBl = buf + 3 * SZ_T + b_lane_off;

#pragma unroll
        for (int ks = 0; ks < 4; ks++) {
            const uint32_t kb = ks * 32;
            uint32_t ah[4], al[4], bh[4][2], bl[4][2];
            LDSM_X4(ah[0], ah[1], ah[2], ah[3], sAh + kb);
            LDSM_X4(al[0], al[1], al[2], al[3], sAl + kb);
#pragma unroll
            for (int ni = 0; ni < 4; ni++) {
                LDSM_X2(bh[ni][0], bh[ni][1], sBh + ni * (8 * AROW) + kb);
                LDSM_X2(bl[ni][0], bl[ni][1], sBl + ni * (8 * AROW) + kb);
            }
#pragma unroll
            for (int ni = 0; ni < 4; ni++) {
                MMA_16816(acc[ni][0], acc[ni][1], acc[ni][2], acc[ni][3],
                          ah[0], ah[1], ah[2], ah[3], bh[ni][0], bh[ni][1]);
                MMA_16816(acc[ni][0], acc[ni][1], acc[ni][2], acc[ni][3],
                          ah[0], ah[1], ah[2], ah[3], bl[ni][0], bl[ni][1]);
                MMA_16816(acc[ni][0], acc[ni][1], acc[ni][2], acc[ni][3],
                          al[0], al[1], al[2], al[3], bh[ni][0], bh[ni][1]);
            }
        }
        __syncthreads();
    }

    const int row = m0 + wm * 16 + (lane >> 2);
#pragma unroll
    for (int ni = 0; ni < 4; ni++) {
        const int col = a0 + wn * 32 + ni * 8 + (lane & 3) * 2;   // even
        const float v0 = acc[ni][0] + bias[col];
        const float v1 = acc[ni][1] + bias[col + 1];
        const float v2 = acc[ni][2] + bias[col];
        const float v3 = acc[ni][3] + bias[col + 1];
        xout[row * ATTN + col]           = v0;
        xout[row * ATTN + col + 1]       = v1;
        xout[(row + 8) * ATTN + col]     = v2;
        xout[(row + 8) * ATTN + col + 1] = v3;
        xouth[row * (ATTN / 2) + (col >> 1)]       = __floats2half2_rn(v0, v1);
        xouth[(row + 8) * (ATTN / 2) + (col >> 1)] = __floats2half2_rn(v2, v3);
    }
}

// ---------------------------------------------------------------------------
// Kernel 2: zero the reduction scratch (also keeps alpha at profile slot #4).
// ---------------------------------------------------------------------------
__global__ __launch_bounds__(512) void zero_kernel()
{
    const int i = blockIdx.x * 512 + threadIdx.x;
    if (i < M1) { g_rowsum[i] = 0.0f; g_colsum[i] = 0.0f; }
}

// ---------------------------------------------------------------------------
// Kernel 3: alpha row/col sums. a-dimension split by 4 (32 pairs/block),
// grid = 576 -> ~4 CTAs/SM. __launch_bounds__(256,4) caps regs at 64 so
// 4 CTAs actually fit (R14 profile: regs=80 allowed only 2-3).
// ---------------------------------------------------------------------------
__global__ __launch_bounds__(256, 4) void alpha_kernel(const float* __restrict__ w)
{
    __shared__ __half2 x1s[16][66];
    __shared__ __half2 x2s[16][66];
    __shared__ __half2 wsm2[32];
    __shared__ float rowp[64];
    __shared__ float colp[64];

    const int tx = threadIdx.x;
    const int ty = threadIdx.y;
    const int tid = ty * 16 + tx;
    const int m0 = blockIdx.y * 64;
    const int n0 = blockIdx.x * 64;
    const int ah0 = blockIdx.z * 32;        // this block's 32 of the 128 pairs

    if (tid < 32)
        wsm2[tid] = __floats2half2_rn(w[2 * (ah0 + tid)], w[2 * (ah0 + tid) + 1]);
    if (tid < 64) { rowp[tid] = 0.0f; colp[tid] = 0.0f; }

    float acc[4][4];
#pragma unroll
    for (int i = 0; i < 4; i++)
#pragma unroll
        for (int j = 0; j < 4; j++) acc[i][j] = 0.0f;

    for (int c = 0; c < 2; c++) {           // 2 chunks of 16 pairs = 32 pairs
        const int a0h = ah0 + c * 16;
        __syncthreads();
#pragma unroll
        for (int it = 0; it < 4; it++) {
            const int idx = tid + it * 256;
            const int p = idx & 15;
            const int r = idx >> 4;
            x1s[p][r] = g_x1h[(m0 + r) * (ATTN / 2) + a0h + p];
            x2s[p][r] = g_x2h[(n0 + r) * (ATTN / 2) + a0h + p];
        }
        __syncthreads();
#pragma unroll
        for (int pp = 0; pp < 16; pp += 4) {
            __half2 hacc[4][4];
#pragma unroll
            for (int i = 0; i < 4; i++)
#pragma unroll
                for (int j = 0; j < 4; j++)
                    hacc[i][j] = __half2half2(__ushort_as_half(0));
#pragma unroll
            for (int p = pp; p < pp + 4; p++) {
                const __half2 w2 = wsm2[c * 16 + p];
                __half2 v1[4], v2[4];
#pragma unroll
                for (int i = 0; i < 4; i++) v1[i] = x1s[p][ty + 16 * i];
#pragma unroll
                for (int j = 0; j < 4; j++) v2[j] = x2s[p][tx + 16 * j];
#pragma unroll
                for (int i = 0; i < 4; i++)
#pragma unroll
                    for (int j = 0; j < 4; j++)
                        hacc[i][j] = __hfma2(w2, tanh2_fast(__hadd2(v1[i], v2[j])), hacc[i][j]);
            }
#pragma unroll
            for (int i = 0; i < 4; i++)
#pragma unroll
                for (int j = 0; j < 4; j++) {
                    const float2 f = __half22float2(hacc[i][j]);
                    acc[i][j] += f.x + f.y;
                }
        }
    }

    __syncthreads();
#pragma unroll
    for (int i = 0; i < 4; i++) {
        float r = acc[i][0] + acc[i][1] + acc[i][2] + acc[i][3];
        atomicAdd(&rowp[ty + 16 * i], r);
    }
#pragma unroll
    for (int j = 0; j < 4; j++) {
        float c = acc[0][j] + acc[1][j] + acc[2][j] + acc[3][j];
        atomicAdd(&colp[tx + 16 * j], c);
    }
    __syncthreads();
    if (tid < 64) {
        atomicAdd(&g_rowsum[m0 + tid], rowp[tid]);
    } else if (tid < 128) {
        atomicAdd(&g_colsum[n0 + tid - 64], colp[tid - 64]);
    }
}

// ---------------------------------------------------------------------------
// Kernel 4: fused epilogue (unchanged).
// ---------------------------------------------------------------------------
__global__ __launch_bounds__(256) void epilogue_kernel(float* __restrict__ out)
{
    __shared__ float pe[M1];
    __shared__ float red[256];

    const int z   = blockIdx.y;
    const int m0  = blockIdx.x * 64;
    const int tid = threadIdx.x;
    const float* __restrict__ sums = z ? g_colsum : g_rowsum;
    const float* __restrict__ x    = z ? g_x2 : g_x1;

    float v[3];
    float lmax = -1e30f;
#pragma unroll
    for (int j = 0; j < 3; j++) {
        v[j] = sums[tid + j * 256] * (1.0f / 768.0f);
        lmax = fmaxf(lmax, v[j]);
    }
    red[tid] = lmax;
    __syncthreads();
    for (int s = 128; s > 0; s >>= 1) {
        if (tid < s) red[tid] = fmaxf(red[tid], red[tid + s]);
        __syncthreads();
    }
    const float mx = red[0];
    __syncthreads();
    float lsum = 0.0f;
#pragma unroll
    for (int j = 0; j < 3; j++) {
        float e = __expf(v[j] - mx);
        pe[tid + j * 256] = e;
        lsum += e;
    }
    red[tid] = lsum;
    __syncthreads();
    for (int s = 128; s > 0; s >>= 1) {
        if (tid < s) red[tid] += red[tid + s];
        __syncthreads();
    }
    const float inv = 1.0f / red[0];
    __syncthreads();

    const int a = tid;
    float s0 = 0.0f, s1 = 0.0f, s2 = 0.0f, s3 = 0.0f;
#pragma unroll 4
    for (int m = 0; m < 64; m += 4) {
        s0 += x[(m0 + m + 0) * ATTN + a] * pe[m0 + m + 0];
        s1 += x[(m0 + m + 1) * ATTN + a] * pe[m0 + m + 1];
        s2 += x[(m0 + m + 2) * ATTN + a] * pe[m0 + m + 2];
        s3 += x[(m0 + m + 3) * ATTN + a] * pe[m0 + m + 3];
    }
    atomicAdd(&out[z * ATTN + a], ((s0 + s1) + (s2 + s3)) * inv);
}

extern "C" void kernel_launch(void* const* d_in, const int* in_sizes, int n_in,
                              void* d_out, int out_size)
{
    const float* h1 = (const float*)d_in[0];
    const float* h2 = (const float*)d_in[1];
    const float* W1 = (const float*)d_in[2];
    const float* b1 = (const float*)d_in[3];
    const float* W2 = (const float*)d_in[4];
    const float* b2 = (const float*)d_in[5];
    const float* w  = (const float*)d_in[6];
    float* out = (float*)d_out;

    cudaFuncSetAttribute(gemm_kernel, cudaFuncAttributeMaxDynamicSharedMemorySize, GEMM_SMEM_BYTES);

    convert_kernel<<<768, 512>>>(h1, h2, W1, W2, out);
    gemm_kernel<<<dim3(ATTN / 64, M1 / 64, 2), 256, GEMM_SMEM_BYTES>>>(b1, b2);
    zero_kernel<<<2, 512>>>();
    alpha_kernel<<<dim3(M2 / 64, M1 / 64, 4), dim3(16, 16)>>>(w);
    epilogue_kernel<<<dim3(M1 / 64, 2), 256>>>(out);
}